// round 4
// baseline (speedup 1.0000x reference)
#include <cuda_runtime.h>
#include <math.h>

#define H    512
#define NH   8
#define DH   64
#define TCTX 10
#define FFD  2048
#define NPREDC 26
#define MAXB 16
#define MAXF 5

__device__ float g_x    [MAXB * MAXF * H];
__device__ float g_qkv  [MAXB * MAXF * 3 * H];
__device__ float g_q    [MAXB * MAXF * H];
__device__ float g_kv   [MAXB * TCTX * 2 * H];
__device__ float g_attno[MAXB * MAXF * H];
__device__ float g_yA   [MAXB * MAXF * H];
__device__ float g_yB   [MAXB * MAXF * H];
__device__ float g_h    [MAXB * MAXF * FFD];
__device__ float g_ctx  [MAXB * MAXF * H];
__device__ float g_Sa   [MAXB * 20 * H];
__device__ float g_Sb   [MAXB * 20 * H];
__device__ float g_Sc   [MAXB * MAXF * H];
__device__ float g_Wc   [27 * H];
__device__ float g_bc   [27];

__device__ __forceinline__ float gelu_f(float x) {
    return 0.5f * x * (1.0f + erff(x * 0.70710678118654752440f));
}

__device__ __forceinline__ void fma2(float2& d, float2 a, float2 b) {
    asm("fma.rn.f32x2 %0, %1, %2, %0;"
        : "+l"(reinterpret_cast<unsigned long long&>(d))
        : "l"(reinterpret_cast<unsigned long long&>(a)),
          "l"(reinterpret_cast<unsigned long long&>(b)));
}

// grid-stride zero (n multiple of 4)
__device__ __forceinline__ void zero_buf(float* p, int n) {
    if (!p) return;
    float4* z = (float4*)p;
    int tot = n >> 2;
    int t = blockIdx.x * blockDim.x + threadIdx.x;
    int str = gridDim.x * blockDim.x;
    for (int i = t; i < tot; i += str) z[i] = make_float4(0.f, 0.f, 0.f, 0.f);
}

// ------------------ broadcast queries + zero init ------------------
__global__ void bcast_kernel(const float* __restrict__ fq, float* __restrict__ x, int Fh,
                             float* z1, int n1, float* z2, int n2, float* z3, int n3) {
    zero_buf(z1, n1); zero_buf(z2, n2); zero_buf(z3, n3);
    int row = blockIdx.x;
    int f = row % Fh;
    int tid = threadIdx.x;   // 128
    #pragma unroll
    for (int i = 0; i < 4; i++) {
        int c = tid + i * 128;
        x[row * H + c] = fq[f * H + c];
    }
}

// ------------------ split-K GEMM, atomic accumulate ------------------
// C += A @ W^T over k-slice [z*kslice, (z+1)*kslice). A:(M,lda) W:(N,ldw)
// if ab != null: a := gelu(a + ab[k]) on load (ff2 path).
// grid (M/16, N/128, K/kslice), 256 threads. kslice % 32 == 0.
__global__ __launch_bounds__(256) void gemm2_kernel(
    const float* __restrict__ A, int lda, const float* __restrict__ ab,
    const float* __restrict__ W, int ldw,
    float* __restrict__ C, int ldc, int kslice)
{
    __shared__ float2 As2[16 * 17];
    __shared__ float2 Ws2[16 * 128];
    int tid = threadIdx.x;
    int row0 = blockIdx.x * 16;
    int n0   = blockIdx.y * 128;
    int kb   = blockIdx.z * kslice;
    int rp = tid >> 5;     // 0..7 -> rows 2rp,2rp+1
    int cg = tid & 31;     // cols 4cg..4cg+3

    float2 acc[2][4];
    #pragma unroll
    for (int j = 0; j < 2; j++)
        #pragma unroll
        for (int q = 0; q < 4; q++) acc[j][q] = make_float2(0.f, 0.f);

    for (int kc = 0; kc < kslice; kc += 32) {
        int k0 = kb + kc;
        if (tid < 128) {
            int r = tid >> 3, kq = tid & 7;
            const float* Ap = A + (size_t)(row0 + r) * lda + k0 + 4 * kq;
            float4 a = *(const float4*)Ap;
            if (ab) {
                const float* bb = ab + k0 + 4 * kq;
                a.x = gelu_f(a.x + bb[0]); a.y = gelu_f(a.y + bb[1]);
                a.z = gelu_f(a.z + bb[2]); a.w = gelu_f(a.w + bb[3]);
            }
            As2[(2 * kq)     * 17 + r] = make_float2(a.x, a.y);
            As2[(2 * kq + 1) * 17 + r] = make_float2(a.z, a.w);
        }
        {
            int n = tid >> 1, hf = tid & 1;
            const float* Wp = W + (size_t)(n0 + n) * ldw + k0 + 16 * hf;
            #pragma unroll
            for (int i = 0; i < 4; i++) {
                float4 w = *(const float4*)(Wp + 4 * i);
                int kp = 8 * hf + 2 * i;
                Ws2[kp * 128 + n]       = make_float2(w.x, w.y);
                Ws2[(kp + 1) * 128 + n] = make_float2(w.z, w.w);
            }
        }
        __syncthreads();
        #pragma unroll
        for (int kp = 0; kp < 16; kp++) {
            float2 a0 = As2[kp * 17 + 2 * rp];
            float2 a1 = As2[kp * 17 + 2 * rp + 1];
            const float4* wp = (const float4*)&Ws2[kp * 128 + 4 * cg];
            float4 wA = wp[0], wB = wp[1];
            float2 w0 = make_float2(wA.x, wA.y), w1 = make_float2(wA.z, wA.w);
            float2 w2 = make_float2(wB.x, wB.y), w3 = make_float2(wB.z, wB.w);
            fma2(acc[0][0], a0, w0); fma2(acc[0][1], a0, w1);
            fma2(acc[0][2], a0, w2); fma2(acc[0][3], a0, w3);
            fma2(acc[1][0], a1, w0); fma2(acc[1][1], a1, w1);
            fma2(acc[1][2], a1, w2); fma2(acc[1][3], a1, w3);
        }
        __syncthreads();
    }

    int n = n0 + 4 * cg;
    #pragma unroll
    for (int j = 0; j < 2; j++) {
        float* Cp = C + (size_t)(row0 + 2 * rp + j) * ldc + n;
        atomicAdd(Cp + 0, acc[j][0].x + acc[j][0].y);
        atomicAdd(Cp + 1, acc[j][1].x + acc[j][1].y);
        atomicAdd(Cp + 2, acc[j][2].x + acc[j][2].y);
        atomicAdd(Cp + 3, acc[j][3].x + acc[j][3].y);
    }
}

// ------------------ attention (tiny T) + zero next buffer ------------------
__global__ void attn_kernel(
    const float* __restrict__ Q, int ldq, const float* __restrict__ qb,
    const float* __restrict__ Kp, const float* __restrict__ Vp, int ldkv,
    const float* __restrict__ kb, const float* __restrict__ vb,
    float* __restrict__ O, int Tq, int Tk,
    float* z1, int n1)
{
    zero_buf(z1, n1);
    int b = blockIdx.x / NH;
    int h = blockIdx.x % NH;
    int qi = threadIdx.x >> 5;
    int lane = threadIdx.x & 31;

    const float* qrow = Q + (size_t)(b * Tq + qi) * ldq + h * DH;
    float q0 = qrow[lane]      + qb[h * DH + lane];
    float q1 = qrow[lane + 32] + qb[h * DH + lane + 32];
    float kb0 = kb[h * DH + lane], kb1 = kb[h * DH + lane + 32];
    float vb0 = vb[h * DH + lane], vb1 = vb[h * DH + lane + 32];

    float s[TCTX];
    #pragma unroll
    for (int k = 0; k < TCTX; k++) {
        if (k < Tk) {
            const float* krow = Kp + (size_t)(b * Tk + k) * ldkv + h * DH;
            float p = q0 * (krow[lane] + kb0) + q1 * (krow[lane + 32] + kb1);
            #pragma unroll
            for (int o = 16; o; o >>= 1) p += __shfl_xor_sync(0xffffffffu, p, o);
            s[k] = p * 0.125f;
        }
    }
    float mx = -1e30f;
    #pragma unroll
    for (int k = 0; k < TCTX; k++) if (k < Tk) mx = fmaxf(mx, s[k]);
    float sum = 0.f;
    #pragma unroll
    for (int k = 0; k < TCTX; k++) if (k < Tk) { s[k] = expf(s[k] - mx); sum += s[k]; }
    float inv = 1.f / sum;
    float o0 = 0.f, o1 = 0.f;
    #pragma unroll
    for (int k = 0; k < TCTX; k++) {
        if (k < Tk) {
            const float* vrow = Vp + (size_t)(b * Tk + k) * ldkv + h * DH;
            float a = s[k] * inv;
            o0 += a * (vrow[lane] + vb0);
            o1 += a * (vrow[lane + 32] + vb1);
        }
    }
    float* orow = O + (size_t)(b * Tq + qi) * H + h * DH;
    orow[lane]      = o0;
    orow[lane + 32] = o1;
}

// ------------------ LayerNorm(src + res + cbias) + zero next buffers --------
__global__ void ln_kernel(const float* __restrict__ src, const float* __restrict__ res,
                          const float* __restrict__ cbias, float* __restrict__ dst,
                          const float* __restrict__ w, const float* __restrict__ b,
                          float* z1, int n1, float* z2, int n2)
{
    zero_buf(z1, n1); zero_buf(z2, n2);
    __shared__ float red[4];
    int row = blockIdx.x;
    int tid = threadIdx.x;   // 128
    int lane = tid & 31, wid = tid >> 5;
    const float* x = src + (size_t)row * H;

    float v[4];
    float s = 0.f;
    #pragma unroll
    for (int i = 0; i < 4; i++) {
        int c = tid + i * 128;
        float t = x[c];
        if (res)   t += res[(size_t)row * H + c];
        if (cbias) t += cbias[c];
        v[i] = t; s += t;
    }
    #pragma unroll
    for (int o = 16; o; o >>= 1) s += __shfl_xor_sync(0xffffffffu, s, o);
    if (lane == 0) red[wid] = s;
    __syncthreads();
    float mean = (red[0] + red[1] + red[2] + red[3]) * (1.0f / H);
    __syncthreads();
    float qv = 0.f;
    #pragma unroll
    for (int i = 0; i < 4; i++) { float d = v[i] - mean; qv += d * d; }
    #pragma unroll
    for (int o = 16; o; o >>= 1) qv += __shfl_xor_sync(0xffffffffu, qv, o);
    if (lane == 0) red[wid] = qv;
    __syncthreads();
    float var = (red[0] + red[1] + red[2] + red[3]) * (1.0f / H);
    float inv = 1.0f / sqrtf(var + 1e-5f);
    #pragma unroll
    for (int i = 0; i < 4; i++) {
        int c = tid + i * 128;
        dst[(size_t)row * H + c] = (v[i] - mean) * inv * w[c] + b[c];
    }
}

// ------------------ Wc = [pred_w;ex_w] @ pe2_w fold ------------------
__global__ void wc_kernel(const float* __restrict__ pred_w, const float* __restrict__ pred_b,
                          const float* __restrict__ ex_w, const float* __restrict__ ex_b,
                          const float* __restrict__ pe2_w, const float* __restrict__ pe2_b,
                          float* __restrict__ Wc, float* __restrict__ bc)
{
    int rr = blockIdx.x;                     // 0..26
    int c = blockIdx.y * 64 + threadIdx.x;   // 0..511
    const float* Prow = (rr < NPREDC) ? (pred_w + rr * H) : ex_w;
    float acc = 0.f;
    for (int n = 0; n < H; n++) acc += Prow[n] * pe2_w[n * H + c];
    Wc[rr * H + c] = acc;
    if (blockIdx.y == 0 && threadIdx.x == 0) {
        float a = 0.f;
        for (int n = 0; n < H; n++) a += Prow[n] * pe2_b[n];
        bc[rr] = a + ((rr < NPREDC) ? pred_b[rr] : ex_b[0]);
    }
}

// ------------------ fused pair epilogue ------------------
__global__ __launch_bounds__(256) void final_kernel(
    const float* __restrict__ Sa, const float* __restrict__ Sb,
    const float* __restrict__ Sc, const float* __restrict__ pe1b,
    const float* __restrict__ Wc, const float* __restrict__ bc,
    float* __restrict__ out_pred, float* __restrict__ out_ex,
    int Nobj, int P, int Fh)
{
    extern __shared__ float sm[];
    float* Wcs = sm;
    float* Scs = sm + 27 * H;
    int bf = blockIdx.y;
    int b = bf / Fh;
    int tid = threadIdx.x;

    for (int i = tid; i < 27 * H; i += 256) Wcs[i] = Wc[i];
    for (int i = tid; i < H; i += 256)      Scs[i] = Sc[bf * H + i] + pe1b[i];
    __syncthreads();

    int w = tid >> 5, lane = tid & 31;
    int p0 = blockIdx.x * 16 + w * 2;
    if (p0 >= P) return;
    int nm1 = Nobj - 1;
    int i0 = p0 / nm1, r0 = p0 % nm1; int j0 = (r0 < i0) ? r0 : r0 + 1;
    int p1 = p0 + 1;
    int i1 = p1 / nm1, r1 = p1 % nm1; int j1 = (r1 < i1) ? r1 : r1 + 1;
    const float* sa0 = Sa + (size_t)(b * Nobj + i0) * H;
    const float* sb0 = Sb + (size_t)(b * Nobj + j0) * H;
    const float* sa1 = Sa + (size_t)(b * Nobj + i1) * H;
    const float* sb1 = Sb + (size_t)(b * Nobj + j1) * H;

    float acc0[27], acc1[27];
    #pragma unroll
    for (int r = 0; r < 27; r++) { acc0[r] = 0.f; acc1[r] = 0.f; }

    #pragma unroll
    for (int jj = 0; jj < 8; jj++) {
        int m = (lane + jj * 32) * 2;
        float2 a0  = *(const float2*)&sa0[m];
        float2 b0v = *(const float2*)&sb0[m];
        float2 a1  = *(const float2*)&sa1[m];
        float2 b1v = *(const float2*)&sb1[m];
        float2 cc  = *(const float2*)&Scs[m];
        float g0x = gelu_f(a0.x + b0v.x + cc.x);
        float g0y = gelu_f(a0.y + b0v.y + cc.y);
        float g1x = gelu_f(a1.x + b1v.x + cc.x);
        float g1y = gelu_f(a1.y + b1v.y + cc.y);
        #pragma unroll
        for (int r = 0; r < 27; r++) {
            float2 wv = *(const float2*)&Wcs[r * H + m];
            acc0[r] += g0x * wv.x + g0y * wv.y;
            acc1[r] += g1x * wv.x + g1y * wv.y;
        }
    }
    #pragma unroll
    for (int r = 0; r < 27; r++) {
        #pragma unroll
        for (int o = 16; o; o >>= 1) {
            acc0[r] += __shfl_xor_sync(0xffffffffu, acc0[r], o);
            acc1[r] += __shfl_xor_sync(0xffffffffu, acc1[r], o);
        }
    }
    float v0 = 0.f, v1 = 0.f;
    #pragma unroll
    for (int r = 0; r < 27; r++) if (lane == r) { v0 = acc0[r]; v1 = acc1[r]; }
    if (lane < 27) {
        float bb = bc[lane];
        v0 += bb; v1 += bb;
        int base0 = bf * P + p0;
        if (lane < NPREDC) {
            out_pred[(size_t)base0 * 26 + lane]       = v0;
            out_pred[(size_t)(base0 + 1) * 26 + lane] = v1;
        } else {
            out_ex[base0]     = v0;
            out_ex[base0 + 1] = v1;
        }
    }
}

// ------------------ host launcher ------------------
extern "C" void kernel_launch(void* const* d_in, const int* in_sizes, int n_in,
                              void* d_out, int out_size)
{
    const float* tc       = (const float*)d_in[0];
    const float* objf     = (const float*)d_in[1];
    const float* fq       = (const float*)d_in[2];
    const float* sa_in_w  = (const float*)d_in[3];
    const float* sa_in_b  = (const float*)d_in[4];
    const float* sa_out_w = (const float*)d_in[5];
    const float* sa_out_b = (const float*)d_in[6];
    const float* ca_in_w  = (const float*)d_in[7];
    const float* ca_in_b  = (const float*)d_in[8];
    const float* ca_out_w = (const float*)d_in[9];
    const float* ca_out_b = (const float*)d_in[10];
    const float* ff1_w    = (const float*)d_in[11];
    const float* ff1_b    = (const float*)d_in[12];
    const float* ff2_w    = (const float*)d_in[13];
    const float* ff2_b    = (const float*)d_in[14];
    const float* n1_w     = (const float*)d_in[15];
    const float* n1_b     = (const float*)d_in[16];
    const float* n2_w     = (const float*)d_in[17];
    const float* n2_b     = (const float*)d_in[18];
    const float* n3_w     = (const float*)d_in[19];
    const float* n3_b     = (const float*)d_in[20];
    const float* norm_w   = (const float*)d_in[21];
    const float* norm_b   = (const float*)d_in[22];
    const float* pe1_w    = (const float*)d_in[23];
    const float* pe1_b    = (const float*)d_in[24];
    const float* pe2_w    = (const float*)d_in[25];
    const float* pe2_b    = (const float*)d_in[26];
    const float* pred_w   = (const float*)d_in[27];
    const float* pred_b   = (const float*)d_in[28];
    const float* ex_w     = (const float*)d_in[29];
    const float* ex_b     = (const float*)d_in[30];

    int B    = in_sizes[0] / (TCTX * H);
    int Nobj = in_sizes[1] / (B * H);
    int P    = Nobj * (Nobj - 1);
    int Fh   = out_size / (B * P * (NPREDC + 1));
    int M    = B * Fh;

    float *gx, *gqkv, *gq, *gkv, *gattno, *gyA, *gyB, *gh, *gctx, *gSa, *gSb, *gSc, *gWc, *gbc;
    cudaGetSymbolAddress((void**)&gx, g_x);       cudaGetSymbolAddress((void**)&gqkv, g_qkv);
    cudaGetSymbolAddress((void**)&gq, g_q);       cudaGetSymbolAddress((void**)&gkv, g_kv);
    cudaGetSymbolAddress((void**)&gattno, g_attno);
    cudaGetSymbolAddress((void**)&gyA, g_yA);     cudaGetSymbolAddress((void**)&gyB, g_yB);
    cudaGetSymbolAddress((void**)&gh, g_h);       cudaGetSymbolAddress((void**)&gctx, g_ctx);
    cudaGetSymbolAddress((void**)&gSa, g_Sa);     cudaGetSymbolAddress((void**)&gSb, g_Sb);
    cudaGetSymbolAddress((void**)&gSc, g_Sc);
    cudaGetSymbolAddress((void**)&gWc, g_Wc);     cudaGetSymbolAddress((void**)&gbc, g_bc);

    int nQKV = M * 3 * H, nY = M * H, nKV = B * TCTX * 2 * H, nHH = M * FFD;
    int nS = B * Nobj * H;

    // independent: Wc fold
    wc_kernel<<<dim3(27, H / 64), 64>>>(pred_w, pred_b, ex_w, ex_b, pe2_w, pe2_b, gWc, gbc);

    // queries + zero gqkv, gSa, gSb
    bcast_kernel<<<M, 128>>>(fq, gx, Fh, gqkv, nQKV, gSa, nS, gSb, nS);

    for (int l = 0; l < 2; l++) {
        const float* siw = sa_in_w  + (size_t)l * 3 * H * H;
        const float* sib = sa_in_b  + (size_t)l * 3 * H;
        const float* sow = sa_out_w + (size_t)l * H * H;
        const float* sob = sa_out_b + (size_t)l * H;
        const float* ciw = ca_in_w  + (size_t)l * 3 * H * H;
        const float* cib = ca_in_b  + (size_t)l * 3 * H;
        const float* cow = ca_out_w + (size_t)l * H * H;
        const float* cob = ca_out_b + (size_t)l * H;
        const float* f1w = ff1_w    + (size_t)l * FFD * H;
        const float* f1b = ff1_b    + (size_t)l * FFD;
        const float* f2w = ff2_w    + (size_t)l * H * FFD;
        const float* f2b = ff2_b    + (size_t)l * H;

        // self-attention
        gemm2_kernel<<<dim3(M / 16, 3 * H / 128, 4), 256>>>(gx, H, nullptr, siw, H, gqkv, 3 * H, 128);
        attn_kernel<<<B * NH, 32 * Fh>>>(gqkv, 3 * H, sib, gqkv + H, gqkv + 2 * H, 3 * H,
                                         sib + H, sib + 2 * H, gattno, Fh, Fh, gyA, nY);
        gemm2_kernel<<<dim3(M / 16, H / 128, 4), 256>>>(gattno, H, nullptr, sow, H, gyA, H, 128);
        ln_kernel<<<M, 128>>>(gyA, gx, sob, gx, n1_w + l * H, n1_b + l * H, gq, nY, gkv, nKV);

        // cross-attention
        gemm2_kernel<<<dim3(M / 16, H / 128, 4), 256>>>(gx, H, nullptr, ciw, H, gq, H, 128);
        gemm2_kernel<<<dim3(B * TCTX / 16, 2 * H / 128, 4), 256>>>(tc, H, nullptr, ciw + (size_t)H * H, H, gkv, 2 * H, 128);
        attn_kernel<<<B * NH, 32 * Fh>>>(gq, H, cib, gkv, gkv + H, 2 * H,
                                         cib + H, cib + 2 * H, gattno, Fh, TCTX, gyB, nY);
        gemm2_kernel<<<dim3(M / 16, H / 128, 4), 256>>>(gattno, H, nullptr, cow, H, gyB, H, 128);
        ln_kernel<<<M, 128>>>(gyB, gx, cob, gx, n2_w + l * H, n2_b + l * H, gh, nHH, gyA, nY);

        // feed-forward (gelu+f1b folded into ff2's A-load)
        gemm2_kernel<<<dim3(M / 16, FFD / 128, 4), 256>>>(gx, H, nullptr, f1w, H, gh, FFD, 128);
        gemm2_kernel<<<dim3(M / 16, H / 128, 16), 256>>>(gh, FFD, f1b, f2w, FFD, gyA, H, 128);
        ln_kernel<<<M, 128>>>(gyA, gx, f2b, gx, n3_w + l * H, n3_b + l * H, gqkv, nQKV, nullptr, 0);
    }

    // final norm + zero Sc
    ln_kernel<<<M, 128>>>(gx, nullptr, nullptr, gctx, norm_w, norm_b, gSc, M * H, nullptr, 0);

    // pe1 factorization (all split-K atomic; targets pre-zeroed)
    gemm2_kernel<<<dim3(B * Nobj / 16, H / 128, 4), 256>>>(objf, H, nullptr, pe1_w,         3 * H, gSa, H, 128);
    gemm2_kernel<<<dim3(B * Nobj / 16, H / 128, 4), 256>>>(objf, H, nullptr, pe1_w + H,     3 * H, gSb, H, 128);
    gemm2_kernel<<<dim3(M / 16,        H / 128, 4), 256>>>(gctx, H, nullptr, pe1_w + 2 * H, 3 * H, gSc, H, 128);

    // fused pair epilogue
    size_t shm = (size_t)(27 * H + H) * sizeof(float);
    cudaFuncSetAttribute(final_kernel, cudaFuncAttributeMaxDynamicSharedMemorySize, (int)shm);
    float* out_pred = (float*)d_out;
    float* out_ex   = out_pred + (size_t)B * Fh * P * NPREDC;
    final_kernel<<<dim3((P + 15) / 16, M), 256, shm>>>(gSa, gSb, gSc, pe1_b, gWc, gbc,
                                                       out_pred, out_ex, Nobj, P, Fh);
}

// round 5
// speedup vs baseline: 1.3448x; 1.3448x over previous
#include <cuda_runtime.h>
#include <math.h>

#define H    512
#define NH   8
#define DH   64
#define TCTX 10
#define FFD  2048
#define NPREDC 26
#define MAXB 16
#define MAXF 5
#define MAXN 20
#define NB   148
#define NT   256

// ------------------------- device scratch -------------------------
__device__ float g_x  [MAXB * MAXF * H];
__device__ float g_ctx[MAXB * MAXF * H];
__device__ float g_qkv[2][MAXB * MAXF * 3 * H];
__device__ float g_qb [2][MAXB * MAXF * H];
__device__ float g_kv [2][MAXB * TCTX * 2 * H];
__device__ float g_ao [MAXB * MAXF * H];
__device__ float g_so [2][MAXB * MAXF * H];
__device__ float g_co [2][MAXB * MAXF * H];
__device__ float g_hh [2][MAXB * MAXF * FFD];
__device__ float g_ff [2][MAXB * MAXF * H];
__device__ float g_Sa [MAXB * MAXN * H];
__device__ float g_Sb [MAXB * MAXN * H];
__device__ float g_Sc [MAXB * MAXF * H];
__device__ float g_Wc [27 * H];
__device__ float g_bc [27];

__device__ unsigned g_count = 0;
__device__ unsigned g_gen   = 0;

struct Params {
    const float *tc, *objf, *fq;
    const float *sa_in_w, *sa_in_b, *sa_out_w, *sa_out_b;
    const float *ca_in_w, *ca_in_b, *ca_out_w, *ca_out_b;
    const float *ff1_w, *ff1_b, *ff2_w, *ff2_b;
    const float *n1_w, *n1_b, *n2_w, *n2_b, *n3_w, *n3_b, *norm_w, *norm_b;
    const float *pe1_w, *pe1_b, *pe2_w, *pe2_b, *pred_w, *pred_b, *ex_w, *ex_b;
    int B, Nobj, Fh;
};

__device__ __forceinline__ float gelu_f(float x) {
    return 0.5f * x * (1.0f + erff(x * 0.70710678118654752440f));
}

__device__ __forceinline__ void fma2(float2& d, float2 a, float2 b) {
    asm("fma.rn.f32x2 %0, %1, %2, %0;"
        : "+l"(reinterpret_cast<unsigned long long&>(d))
        : "l"(reinterpret_cast<unsigned long long&>(a)),
          "l"(reinterpret_cast<unsigned long long&>(b)));
}

// grid barrier: counting arrive + generation release (resets each use)
__device__ __forceinline__ void gsync() {
    __syncthreads();
    if (threadIdx.x == 0) {
        __threadfence();
        unsigned gen = *((volatile unsigned*)&g_gen);
        if (atomicAdd(&g_count, 1) == NB - 1) {
            g_count = 0;
            __threadfence();
            atomicAdd(&g_gen, 1);
        } else {
            while (*((volatile unsigned*)&g_gen) == gen) { __nanosleep(32); }
            __threadfence();
        }
    }
    __syncthreads();
}

// one 16x128 output tile over a 128-wide K slice; atomic accumulate.
// if ab: A := gelu(A + ab[k]) on load.
__device__ void gemm_unit(const float* __restrict__ A, int lda, const float* __restrict__ ab,
                          const float* __restrict__ W, int ldw,
                          float* __restrict__ C, int ldc,
                          int row0, int n0, int kb,
                          float2* As2, float2* Ws2, int tid)
{
    int rp = tid >> 5, cg = tid & 31;
    float2 acc[2][4];
    #pragma unroll
    for (int j = 0; j < 2; j++)
        #pragma unroll
        for (int q = 0; q < 4; q++) acc[j][q] = make_float2(0.f, 0.f);

    for (int kc = 0; kc < 128; kc += 32) {
        int k0 = kb + kc;
        if (tid < 128) {
            int r = tid >> 3, kq = tid & 7;
            const float* Ap = A + (size_t)(row0 + r) * lda + k0 + 4 * kq;
            float4 a = *(const float4*)Ap;
            if (ab) {
                const float* bb = ab + k0 + 4 * kq;
                a.x = gelu_f(a.x + bb[0]); a.y = gelu_f(a.y + bb[1]);
                a.z = gelu_f(a.z + bb[2]); a.w = gelu_f(a.w + bb[3]);
            }
            As2[(2 * kq)     * 17 + r] = make_float2(a.x, a.y);
            As2[(2 * kq + 1) * 17 + r] = make_float2(a.z, a.w);
        }
        {
            int n = tid >> 1, hf = tid & 1;
            const float* Wp = W + (size_t)(n0 + n) * ldw + k0 + 16 * hf;
            #pragma unroll
            for (int i = 0; i < 4; i++) {
                float4 w = *(const float4*)(Wp + 4 * i);
                int kp = 8 * hf + 2 * i;
                Ws2[kp * 128 + n]       = make_float2(w.x, w.y);
                Ws2[(kp + 1) * 128 + n] = make_float2(w.z, w.w);
            }
        }
        __syncthreads();
        #pragma unroll
        for (int kp = 0; kp < 16; kp++) {
            float2 a0 = As2[kp * 17 + 2 * rp];
            float2 a1 = As2[kp * 17 + 2 * rp + 1];
            const float4* wp = (const float4*)&Ws2[kp * 128 + 4 * cg];
            float4 wA = wp[0], wB = wp[1];
            float2 w0 = make_float2(wA.x, wA.y), w1 = make_float2(wA.z, wA.w);
            float2 w2 = make_float2(wB.x, wB.y), w3 = make_float2(wB.z, wB.w);
            fma2(acc[0][0], a0, w0); fma2(acc[0][1], a0, w1);
            fma2(acc[0][2], a0, w2); fma2(acc[0][3], a0, w3);
            fma2(acc[1][0], a1, w0); fma2(acc[1][1], a1, w1);
            fma2(acc[1][2], a1, w2); fma2(acc[1][3], a1, w3);
        }
        __syncthreads();
    }
    int n = n0 + 4 * cg;
    #pragma unroll
    for (int j = 0; j < 2; j++) {
        float* Cp = C + (size_t)(row0 + 2 * rp + j) * ldc + n;
        atomicAdd(Cp + 0, acc[j][0].x + acc[j][0].y);
        atomicAdd(Cp + 1, acc[j][1].x + acc[j][1].y);
        atomicAdd(Cp + 2, acc[j][2].x + acc[j][2].y);
        atomicAdd(Cp + 3, acc[j][3].x + acc[j][3].y);
    }
}

// ------------------------- persistent decoder -------------------------
__global__ __launch_bounds__(NT, 2) void decoder_kernel(Params p)
{
    __shared__ float2 sA[16 * 17];
    __shared__ float2 sW[16 * 128];
    const int tid = threadIdx.x, bid = blockIdx.x;
    const int lane = tid & 31;
    const int gw = bid * (NT / 32) + (tid >> 5);
    const int GW = NB * (NT / 32);
    const int M = p.B * p.Fh;
    const int Fh = p.Fh;

    auto zero4 = [&](float* pz, int n) {
        float4* z = (float4*)pz;
        int t4 = n >> 2;
        for (int i = bid * NT + tid; i < t4; i += NB * NT)
            z[i] = make_float4(0.f, 0.f, 0.f, 0.f);
    };
    auto gemm_stage = [&](const float* A, int lda, const float* ab,
                          const float* W, int ldw, float* C, int ldc,
                          int mt, int nt, int kz) {
        int total = mt * nt * kz;
        for (int u = bid; u < total; u += NB) {
            int m = u % mt; int n = (u / mt) % nt; int z = u / (mt * nt);
            gemm_unit(A, lda, ab, W, ldw, C, ldc, m * 16, n * 128, z * 128, sA, sW, tid);
        }
    };
    auto attn_stage = [&](const float* Q, int ldq, const float* qb,
                          const float* K, const float* V, int ldkv,
                          const float* kb, const float* vb, int Tq, int Tk) {
        for (int u = gw; u < p.B * NH * Tq; u += GW) {
            int qi = u % Tq; int h = (u / Tq) % NH; int b = u / (Tq * NH);
            const float* qrow = Q + (size_t)(b * Tq + qi) * ldq + h * DH;
            float q0 = qrow[lane]      + qb[h * DH + lane];
            float q1 = qrow[lane + 32] + qb[h * DH + lane + 32];
            float kb0 = kb[h * DH + lane], kb1 = kb[h * DH + lane + 32];
            float vb0 = vb[h * DH + lane], vb1 = vb[h * DH + lane + 32];
            float s[TCTX];
            #pragma unroll
            for (int k = 0; k < TCTX; k++) {
                if (k < Tk) {
                    const float* krow = K + (size_t)(b * Tk + k) * ldkv + h * DH;
                    float pr = q0 * (krow[lane] + kb0) + q1 * (krow[lane + 32] + kb1);
                    #pragma unroll
                    for (int o = 16; o; o >>= 1) pr += __shfl_xor_sync(0xffffffffu, pr, o);
                    s[k] = pr * 0.125f;
                }
            }
            float mx = -1e30f;
            #pragma unroll
            for (int k = 0; k < TCTX; k++) if (k < Tk) mx = fmaxf(mx, s[k]);
            float sum = 0.f;
            #pragma unroll
            for (int k = 0; k < TCTX; k++) if (k < Tk) { s[k] = expf(s[k] - mx); sum += s[k]; }
            float inv = 1.f / sum;
            float o0 = 0.f, o1 = 0.f;
            #pragma unroll
            for (int k = 0; k < TCTX; k++) {
                if (k < Tk) {
                    const float* vrow = V + (size_t)(b * Tk + k) * ldkv + h * DH;
                    float a = s[k] * inv;
                    o0 += a * (vrow[lane] + vb0);
                    o1 += a * (vrow[lane + 32] + vb1);
                }
            }
            float* orow = g_ao + (size_t)(b * Tq + qi) * H + h * DH;
            orow[lane]      = o0;
            orow[lane + 32] = o1;
        }
    };
    auto ln_stage = [&](const float* src, const float* res, const float* cb,
                        float* dst, const float* w, const float* bnb) {
        for (int row = gw; row < M; row += GW) {
            const float* xr = src + (size_t)row * H;
            float4 v[4];
            float s = 0.f;
            #pragma unroll
            for (int i = 0; i < 4; i++) {
                int c = i * 128 + lane * 4;
                float4 t = *(const float4*)&xr[c];
                if (res) { float4 r = *(const float4*)&res[(size_t)row * H + c];
                           t.x += r.x; t.y += r.y; t.z += r.z; t.w += r.w; }
                if (cb)  { float4 b4 = *(const float4*)&cb[c];
                           t.x += b4.x; t.y += b4.y; t.z += b4.z; t.w += b4.w; }
                v[i] = t; s += t.x + t.y + t.z + t.w;
            }
            #pragma unroll
            for (int o = 16; o; o >>= 1) s += __shfl_xor_sync(0xffffffffu, s, o);
            float mean = s * (1.0f / H);
            float q = 0.f;
            #pragma unroll
            for (int i = 0; i < 4; i++) {
                float dx = v[i].x - mean, dy = v[i].y - mean, dz = v[i].z - mean, dw = v[i].w - mean;
                q += dx * dx + dy * dy + dz * dz + dw * dw;
            }
            #pragma unroll
            for (int o = 16; o; o >>= 1) q += __shfl_xor_sync(0xffffffffu, q, o);
            float var = q * (1.0f / H);
            float inv = 1.0f / sqrtf(var + 1e-5f);
            #pragma unroll
            for (int i = 0; i < 4; i++) {
                int c = i * 128 + lane * 4;
                float4 w4 = *(const float4*)&w[c];
                float4 b4 = *(const float4*)&bnb[c];
                float4 o4;
                o4.x = (v[i].x - mean) * inv * w4.x + b4.x;
                o4.y = (v[i].y - mean) * inv * w4.y + b4.y;
                o4.z = (v[i].z - mean) * inv * w4.z + b4.z;
                o4.w = (v[i].w - mean) * inv * w4.w + b4.w;
                *(float4*)&dst[(size_t)row * H + c] = o4;
            }
        }
    };

    // ---- Z0: zero scratch, broadcast queries, fold Wc/bc ----
    zero4(g_qkv[0], M * 3 * H);  zero4(g_qkv[1], M * 3 * H);
    zero4(g_qb[0],  M * H);      zero4(g_qb[1],  M * H);
    zero4(g_kv[0],  p.B * TCTX * 2 * H); zero4(g_kv[1], p.B * TCTX * 2 * H);
    zero4(g_so[0],  M * H);      zero4(g_so[1],  M * H);
    zero4(g_co[0],  M * H);      zero4(g_co[1],  M * H);
    zero4(g_hh[0],  M * FFD);    zero4(g_hh[1],  M * FFD);
    zero4(g_ff[0],  M * H);      zero4(g_ff[1],  M * H);
    zero4(g_Sa, p.B * p.Nobj * H); zero4(g_Sb, p.B * p.Nobj * H);
    zero4(g_Sc, M * H);
    for (int i = bid * NT + tid; i < M * H; i += NB * NT) {
        int row = i / H, c = i % H;
        g_x[i] = p.fq[(row % Fh) * H + c];
    }
    for (int i = bid * NT + tid; i < 27 * H; i += NB * NT) {
        int rr = i / H, c = i % H;
        const float* Pr = (rr < NPREDC) ? (p.pred_w + rr * H) : p.ex_w;
        float acc = 0.f;
        #pragma unroll 4
        for (int n = 0; n < H; n++) acc += Pr[n] * p.pe2_w[n * H + c];
        g_Wc[i] = acc;
    }
    if (bid == 0 && tid < 27) {
        const float* Pr = (tid < NPREDC) ? (p.pred_w + tid * H) : p.ex_w;
        float a = 0.f;
        for (int n = 0; n < H; n++) a += Pr[n] * p.pe2_b[n];
        g_bc[tid] = a + ((tid < NPREDC) ? p.pred_b[tid] : p.ex_b[0]);
    }
    gsync();

    // ---- S1: qkv0 + Sa + Sb + kv0 ----
    gemm_stage(g_x, H, nullptr, p.sa_in_w, H, g_qkv[0], 3 * H, M / 16, 3 * H / 128, 4);
    gemm_stage(p.objf, H, nullptr, p.pe1_w,     3 * H, g_Sa, H, (p.B * p.Nobj) / 16, 4, 4);
    gemm_stage(p.objf, H, nullptr, p.pe1_w + H, 3 * H, g_Sb, H, (p.B * p.Nobj) / 16, 4, 4);
    gemm_stage(p.tc, H, nullptr, p.ca_in_w + (size_t)H * H, H, g_kv[0], 2 * H, (p.B * TCTX) / 16, 2 * H / 128, 4);
    gsync();

    for (int l = 0; l < 2; l++) {
        const float* siw = p.sa_in_w  + (size_t)l * 3 * H * H;
        const float* sib = p.sa_in_b  + (size_t)l * 3 * H;
        const float* sow = p.sa_out_w + (size_t)l * H * H;
        const float* sob = p.sa_out_b + (size_t)l * H;
        const float* ciw = p.ca_in_w  + (size_t)l * 3 * H * H;
        const float* cib = p.ca_in_b  + (size_t)l * 3 * H;
        const float* cow = p.ca_out_w + (size_t)l * H * H;
        const float* cob = p.ca_out_b + (size_t)l * H;
        const float* f1w = p.ff1_w    + (size_t)l * FFD * H;
        const float* f1b = p.ff1_b    + (size_t)l * FFD;
        const float* f2w = p.ff2_w    + (size_t)l * H * FFD;
        const float* f2b = p.ff2_b    + (size_t)l * H;

        if (l == 1) {
            gemm_stage(g_x, H, nullptr, siw, H, g_qkv[1], 3 * H, M / 16, 3 * H / 128, 4);
            gemm_stage(p.tc, H, nullptr, ciw + (size_t)H * H, H, g_kv[1], 2 * H, (p.B * TCTX) / 16, 2 * H / 128, 4);
            gsync();
        }
        // self-attention
        attn_stage(g_qkv[l], 3 * H, sib, g_qkv[l] + H, g_qkv[l] + 2 * H, 3 * H,
                   sib + H, sib + 2 * H, Fh, Fh);
        gsync();
        gemm_stage(g_ao, H, nullptr, sow, H, g_so[l], H, M / 16, 4, 4);
        gsync();
        ln_stage(g_so[l], g_x, sob, g_x, p.n1_w + l * H, p.n1_b + l * H);
        gsync();
        // cross-attention
        gemm_stage(g_x, H, nullptr, ciw, H, g_qb[l], H, M / 16, 4, 4);
        gsync();
        attn_stage(g_qb[l], H, cib, g_kv[l], g_kv[l] + H, 2 * H,
                   cib + H, cib + 2 * H, Fh, TCTX);
        gsync();
        gemm_stage(g_ao, H, nullptr, cow, H, g_co[l], H, M / 16, 4, 4);
        gsync();
        ln_stage(g_co[l], g_x, cob, g_x, p.n2_w + l * H, p.n2_b + l * H);
        gsync();
        // feed-forward (gelu+f1b folded into ff2 A-load)
        gemm_stage(g_x, H, nullptr, f1w, H, g_hh[l], FFD, M / 16, FFD / 128, 4);
        gsync();
        gemm_stage(g_hh[l], FFD, f1b, f2w, FFD, g_ff[l], H, M / 16, 4, FFD / 128);
        gsync();
        ln_stage(g_ff[l], g_x, f2b, g_x, p.n3_w + l * H, p.n3_b + l * H);
        gsync();
    }

    // final LN + Sc GEMM
    ln_stage(g_x, nullptr, nullptr, g_ctx, p.norm_w, p.norm_b);
    gsync();
    gemm_stage(g_ctx, H, nullptr, p.pe1_w + 2 * H, 3 * H, g_Sc, H, M / 16, 4, 4);
    // kernel end = device-wide completion before next launch
}

// ------------------------- fused pair epilogue -------------------------
__global__ __launch_bounds__(256) void final_kernel(
    const float* __restrict__ pe1b,
    float* __restrict__ out_pred, float* __restrict__ out_ex,
    int Nobj, int P, int Fh)
{
    extern __shared__ float sm[];
    float* Wcs = sm;
    float* Scs = sm + 27 * H;
    int bf = blockIdx.y;
    int b = bf / Fh;
    int tid = threadIdx.x;

    for (int i = tid; i < 27 * H; i += 256) Wcs[i] = g_Wc[i];
    for (int i = tid; i < H; i += 256)      Scs[i] = g_Sc[bf * H + i] + pe1b[i];
    __syncthreads();

    int w = tid >> 5, lane = tid & 31;
    int p0 = blockIdx.x * 16 + w * 2;
    if (p0 >= P) return;
    int nm1 = Nobj - 1;
    int i0 = p0 / nm1, r0 = p0 % nm1; int j0 = (r0 < i0) ? r0 : r0 + 1;
    int p1 = p0 + 1;
    int i1 = p1 / nm1, r1 = p1 % nm1; int j1 = (r1 < i1) ? r1 : r1 + 1;
    const float* sa0 = g_Sa + (size_t)(b * Nobj + i0) * H;
    const float* sb0 = g_Sb + (size_t)(b * Nobj + j0) * H;
    const float* sa1 = g_Sa + (size_t)(b * Nobj + i1) * H;
    const float* sb1 = g_Sb + (size_t)(b * Nobj + j1) * H;

    float acc0[27], acc1[27];
    #pragma unroll
    for (int r = 0; r < 27; r++) { acc0[r] = 0.f; acc1[r] = 0.f; }

    #pragma unroll
    for (int jj = 0; jj < 8; jj++) {
        int m = (lane + jj * 32) * 2;
        float2 a0  = *(const float2*)&sa0[m];
        float2 b0v = *(const float2*)&sb0[m];
        float2 a1  = *(const float2*)&sa1[m];
        float2 b1v = *(const float2*)&sb1[m];
        float2 cc  = *(const float2*)&Scs[m];
        float g0x = gelu_f(a0.x + b0v.x + cc.x);
        float g0y = gelu_f(a0.y + b0v.y + cc.y);
        float g1x = gelu_f(a1.x + b1v.x + cc.x);
        float g1y = gelu_f(a1.y + b1v.y + cc.y);
        #pragma unroll
        for (int r = 0; r < 27; r++) {
            float2 wv = *(const float2*)&Wcs[r * H + m];
            acc0[r] += g0x * wv.x + g0y * wv.y;
            acc1[r] += g1x * wv.x + g1y * wv.y;
        }
    }
    #pragma unroll
    for (int r = 0; r < 27; r++) {
        #pragma unroll
        for (int o = 16; o; o >>= 1) {
            acc0[r] += __shfl_xor_sync(0xffffffffu, acc0[r], o);
            acc1[r] += __shfl_xor_sync(0xffffffffu, acc1[r], o);
        }
    }
    float v0 = 0.f, v1 = 0.f;
    #pragma unroll
    for (int r = 0; r < 27; r++) if (lane == r) { v0 = acc0[r]; v1 = acc1[r]; }
    if (lane < 27) {
        float bb = g_bc[lane];
        v0 += bb; v1 += bb;
        int base0 = bf * P + p0;
        if (lane < NPREDC) {
            out_pred[(size_t)base0 * 26 + lane]       = v0;
            out_pred[(size_t)(base0 + 1) * 26 + lane] = v1;
        } else {
            out_ex[base0]     = v0;
            out_ex[base0 + 1] = v1;
        }
    }
}

// ------------------------- host launcher -------------------------
extern "C" void kernel_launch(void* const* d_in, const int* in_sizes, int n_in,
                              void* d_out, int out_size)
{
    Params p;
    p.tc       = (const float*)d_in[0];
    p.objf     = (const float*)d_in[1];
    p.fq       = (const float*)d_in[2];
    p.sa_in_w  = (const float*)d_in[3];
    p.sa_in_b  = (const float*)d_in[4];
    p.sa_out_w = (const float*)d_in[5];
    p.sa_out_b = (const float*)d_in[6];
    p.ca_in_w  = (const float*)d_in[7];
    p.ca_in_b  = (const float*)d_in[8];
    p.ca_out_w = (const float*)d_in[9];
    p.ca_out_b = (const float*)d_in[10];
    p.ff1_w    = (const float*)d_in[11];
    p.ff1_b    = (const float*)d_in[12];
    p.ff2_w    = (const float*)d_in[13];
    p.ff2_b    = (const float*)d_in[14];
    p.n1_w     = (const float*)d_in[15];
    p.n1_b     = (const float*)d_in[16];
    p.n2_w     = (const float*)d_in[17];
    p.n2_b     = (const float*)d_in[18];
    p.n3_w     = (const float*)d_in[19];
    p.n3_b     = (const float*)d_in[20];
    p.norm_w   = (const float*)d_in[21];
    p.norm_b   = (const float*)d_in[22];
    p.pe1_w    = (const float*)d_in[23];
    p.pe1_b    = (const float*)d_in[24];
    p.pe2_w    = (const float*)d_in[25];
    p.pe2_b    = (const float*)d_in[26];
    p.pred_w   = (const float*)d_in[27];
    p.pred_b   = (const float*)d_in[28];
    p.ex_w     = (const float*)d_in[29];
    p.ex_b     = (const float*)d_in[30];

    p.B    = in_sizes[0] / (TCTX * H);
    p.Nobj = in_sizes[1] / (p.B * H);
    int P  = p.Nobj * (p.Nobj - 1);
    p.Fh   = out_size / (p.B * P * (NPREDC + 1));
    int M  = p.B * p.Fh;

    decoder_kernel<<<NB, NT>>>(p);

    size_t shm = (size_t)(27 * H + H) * sizeof(float);
    cudaFuncSetAttribute(final_kernel, cudaFuncAttributeMaxDynamicSharedMemorySize, (int)shm);
    float* out_pred = (float*)d_out;
    float* out_ex   = out_pred + (size_t)p.B * p.Fh * P * NPREDC;
    final_kernel<<<dim3((P + 15) / 16, M), 256, shm>>>(p.pe1_b, out_pred, out_ex,
                                                       p.Nobj, P, p.Fh);
}

// round 7
// speedup vs baseline: 1.3536x; 1.0065x over previous
#include <cuda_runtime.h>
#include <math.h>

#define H    512
#define NH   8
#define DH   64
#define TCTX 10
#define FFD  2048
#define NPREDC 26
#define MAXB 16
#define MAXF 5
#define MAXN 20
#define NB   296
#define NT   256

// ------------------------- device scratch -------------------------
__device__ float g_x  [MAXB * MAXF * H];
__device__ float g_ctx[MAXB * MAXF * H];
__device__ float g_qkv[2][MAXB * MAXF * 3 * H];
__device__ float g_qb [2][MAXB * MAXF * H];
__device__ float g_kv [2][MAXB * TCTX * 2 * H];
__device__ float g_ao [MAXB * MAXF * H];
__device__ float g_so [2][MAXB * MAXF * H];
__device__ float g_co [2][MAXB * MAXF * H];
__device__ float g_hh [2][MAXB * MAXF * FFD];
__device__ float g_ff [2][MAXB * MAXF * H];
__device__ float g_Sa [MAXB * MAXN * H];
__device__ float g_Sb [MAXB * MAXN * H];
__device__ float g_Sc [MAXB * MAXF * H];
__device__ float g_Wc [27 * H];
__device__ float g_bc [27];

__device__ unsigned g_count = 0;
__device__ unsigned g_gen   = 0;

struct Params {
    const float *tc, *objf, *fq;
    const float *sa_in_w, *sa_in_b, *sa_out_w, *sa_out_b;
    const float *ca_in_w, *ca_in_b, *ca_out_w, *ca_out_b;
    const float *ff1_w, *ff1_b, *ff2_w, *ff2_b;
    const float *n1_w, *n1_b, *n2_w, *n2_b, *n3_w, *n3_b, *norm_w, *norm_b;
    const float *pe1_w, *pe1_b, *pe2_w, *pe2_b, *pred_w, *pred_b, *ex_w, *ex_b;
    int B, Nobj, Fh;
};

__device__ __forceinline__ float gelu_f(float x) {
    return 0.5f * x * (1.0f + erff(x * 0.70710678118654752440f));
}

__device__ __forceinline__ void fma2(float2& d, float2 a, float2 b) {
    asm("fma.rn.f32x2 %0, %1, %2, %0;"
        : "+l"(reinterpret_cast<unsigned long long&>(d))
        : "l"(reinterpret_cast<unsigned long long&>(a)),
          "l"(reinterpret_cast<unsigned long long&>(b)));
}

__device__ __forceinline__ void gsync() {
    __syncthreads();
    if (threadIdx.x == 0) {
        __threadfence();
        unsigned gen = *((volatile unsigned*)&g_gen);
        if (atomicAdd(&g_count, 1) == gridDim.x - 1) {
            g_count = 0;
            __threadfence();
            atomicAdd(&g_gen, 1);
        } else {
            while (*((volatile unsigned*)&g_gen) == gen) { __nanosleep(32); }
            __threadfence();
        }
    }
    __syncthreads();
}

// ---- 16x128 GEMM tile over a 128-wide K slice, atomic out (R5-verified
// layout; register prefetch of the next chunk hoisted before compute) ----
__device__ void gemm_unit(const float* __restrict__ A, int lda, const float* __restrict__ ab,
                          const float* __restrict__ W, int ldw,
                          float* __restrict__ C, int ldc,
                          int row0, int n0, int kb,
                          float2* As2, float2* Ws2, int tid)
{
    const int rp = tid >> 5;      // 0..7 -> rows 2rp, 2rp+1
    const int cg = tid & 31;      // cols 4cg..4cg+3
    float2 acc[2][4];
    #pragma unroll
    for (int j = 0; j < 2; j++)
        #pragma unroll
        for (int q = 0; q < 4; q++) acc[j][q] = make_float2(0.f, 0.f);

    const int alr = tid >> 3, alk = tid & 7;   // A load: row 0..15, float4 slot
    const int wn  = tid >> 1, whf = tid & 1;   // W load: row 0..127, half
    float4 ar; float4 wr[4];

    auto loadRegs = [&](int k0) {
        if (tid < 128) {
            ar = *(const float4*)(A + (size_t)(row0 + alr) * lda + k0 + 4 * alk);
            if (ab) {
                const float* bb = ab + k0 + 4 * alk;
                ar.x = gelu_f(ar.x + bb[0]); ar.y = gelu_f(ar.y + bb[1]);
                ar.z = gelu_f(ar.z + bb[2]); ar.w = gelu_f(ar.w + bb[3]);
            }
        }
        const float* Wp = W + (size_t)(n0 + wn) * ldw + k0 + 16 * whf;
        #pragma unroll
        for (int i = 0; i < 4; i++) wr[i] = *(const float4*)(Wp + 4 * i);
    };
    auto storeRegs = [&]() {
        if (tid < 128) {
            As2[(2 * alk)     * 17 + alr] = make_float2(ar.x, ar.y);
            As2[(2 * alk + 1) * 17 + alr] = make_float2(ar.z, ar.w);
        }
        #pragma unroll
        for (int i = 0; i < 4; i++) {
            int kp = 8 * whf + 2 * i;
            Ws2[kp * 128 + wn]       = make_float2(wr[i].x, wr[i].y);
            Ws2[(kp + 1) * 128 + wn] = make_float2(wr[i].z, wr[i].w);
        }
    };

    loadRegs(kb);
    #pragma unroll
    for (int c = 0; c < 4; c++) {
        storeRegs();
        __syncthreads();
        if (c < 3) loadRegs(kb + 32 * (c + 1));   // prefetch next chunk
        #pragma unroll
        for (int kp = 0; kp < 16; kp++) {
            float2 a0 = As2[kp * 17 + 2 * rp];
            float2 a1 = As2[kp * 17 + 2 * rp + 1];
            const float4* wp4 = (const float4*)&Ws2[kp * 128 + 4 * cg];
            float4 w01 = wp4[0];
            float4 w23 = wp4[1];
            float2 wa = make_float2(w01.x, w01.y);
            float2 wb = make_float2(w01.z, w01.w);
            float2 wc = make_float2(w23.x, w23.y);
            float2 wd = make_float2(w23.z, w23.w);
            fma2(acc[0][0], a0, wa); fma2(acc[0][1], a0, wb);
            fma2(acc[0][2], a0, wc); fma2(acc[0][3], a0, wd);
            fma2(acc[1][0], a1, wa); fma2(acc[1][1], a1, wb);
            fma2(acc[1][2], a1, wc); fma2(acc[1][3], a1, wd);
        }
        __syncthreads();
    }

    int n = n0 + 4 * cg;
    #pragma unroll
    for (int j = 0; j < 2; j++) {
        float* Cp = C + (size_t)(row0 + 2 * rp + j) * ldc + n;
        atomicAdd(Cp + 0, acc[j][0].x + acc[j][0].y);
        atomicAdd(Cp + 1, acc[j][1].x + acc[j][1].y);
        atomicAdd(Cp + 2, acc[j][2].x + acc[j][2].y);
        atomicAdd(Cp + 3, acc[j][3].x + acc[j][3].y);
    }
}

// ------------------------- persistent decoder -------------------------
__global__ __launch_bounds__(NT, 2) void decoder_kernel(Params p)
{
    __shared__ float2 sA[16 * 17];
    __shared__ float2 sW[16 * 128];
    const int tid = threadIdx.x, bid = blockIdx.x;
    const int lane = tid & 31;
    const int gw = bid * (NT / 32) + (tid >> 5);
    const int GW = gridDim.x * (NT / 32);
    const int GB = gridDim.x;
    const int M = p.B * p.Fh;
    const int Fh = p.Fh;

    auto zero4 = [&](float* pz, int n) {
        float4* z = (float4*)pz;
        int t4 = n >> 2;
        for (int i = bid * NT + tid; i < t4; i += GB * NT)
            z[i] = make_float4(0.f, 0.f, 0.f, 0.f);
    };
    auto gemm_stage = [&](const float* A, int lda, const float* ab,
                          const float* W, int ldw, float* C, int ldc,
                          int mt, int nt, int kz) {
        int total = mt * nt * kz;
        for (int u = bid; u < total; u += GB) {
            int m = u % mt; int n = (u / mt) % nt; int z = u / (mt * nt);
            gemm_unit(A, lda, ab, W, ldw, C, ldc, m * 16, n * 128, z * 128, sA, sW, tid);
        }
    };
    auto attn_stage = [&](const float* Q, int ldq, const float* qb,
                          const float* K, const float* V, int ldkv,
                          const float* kb, const float* vb, int Tq, int Tk) {
        for (int u = gw; u < p.B * NH * Tq; u += GW) {
            int qi = u % Tq; int h = (u / Tq) % NH; int b = u / (Tq * NH);
            const float* qrow = Q + (size_t)(b * Tq + qi) * ldq + h * DH;
            float q0 = qrow[lane]      + qb[h * DH + lane];
            float q1 = qrow[lane + 32] + qb[h * DH + lane + 32];
            float kb0 = kb[h * DH + lane], kb1 = kb[h * DH + lane + 32];
            float vb0 = vb[h * DH + lane], vb1 = vb[h * DH + lane + 32];
            float s[TCTX];
            #pragma unroll
            for (int k = 0; k < TCTX; k++) {
                if (k < Tk) {
                    const float* krow = K + (size_t)(b * Tk + k) * ldkv + h * DH;
                    float pr = q0 * (krow[lane] + kb0) + q1 * (krow[lane + 32] + kb1);
                    #pragma unroll
                    for (int o = 16; o; o >>= 1) pr += __shfl_xor_sync(0xffffffffu, pr, o);
                    s[k] = pr * 0.125f;
                }
            }
            float mx = -1e30f;
            #pragma unroll
            for (int k = 0; k < TCTX; k++) if (k < Tk) mx = fmaxf(mx, s[k]);
            float sum = 0.f;
            #pragma unroll
            for (int k = 0; k < TCTX; k++) if (k < Tk) { s[k] = expf(s[k] - mx); sum += s[k]; }
            float inv = 1.f / sum;
            float o0 = 0.f, o1 = 0.f;
            #pragma unroll
            for (int k = 0; k < TCTX; k++) {
                if (k < Tk) {
                    const float* vrow = V + (size_t)(b * Tk + k) * ldkv + h * DH;
                    float a = s[k] * inv;
                    o0 += a * (vrow[lane] + vb0);
                    o1 += a * (vrow[lane + 32] + vb1);
                }
            }
            float* orow = g_ao + (size_t)(b * Tq + qi) * H + h * DH;
            orow[lane]      = o0;
            orow[lane + 32] = o1;
        }
    };
    auto ln_stage = [&](const float* src, const float* res, const float* cb,
                        float* dst, const float* w, const float* bnb) {
        for (int row = gw; row < M; row += GW) {
            const float* xr = src + (size_t)row * H;
            float4 v[4];
            float s = 0.f;
            #pragma unroll
            for (int i = 0; i < 4; i++) {
                int c = i * 128 + lane * 4;
                float4 t = *(const float4*)&xr[c];
                if (res) { float4 r = *(const float4*)&res[(size_t)row * H + c];
                           t.x += r.x; t.y += r.y; t.z += r.z; t.w += r.w; }
                if (cb)  { float4 b4 = *(const float4*)&cb[c];
                           t.x += b4.x; t.y += b4.y; t.z += b4.z; t.w += b4.w; }
                v[i] = t; s += t.x + t.y + t.z + t.w;
            }
            #pragma unroll
            for (int o = 16; o; o >>= 1) s += __shfl_xor_sync(0xffffffffu, s, o);
            float mean = s * (1.0f / H);
            float q = 0.f;
            #pragma unroll
            for (int i = 0; i < 4; i++) {
                float dx = v[i].x - mean, dy = v[i].y - mean, dz = v[i].z - mean, dw = v[i].w - mean;
                q += dx * dx + dy * dy + dz * dz + dw * dw;
            }
            #pragma unroll
            for (int o = 16; o; o >>= 1) q += __shfl_xor_sync(0xffffffffu, q, o);
            float inv = 1.0f / sqrtf(q * (1.0f / H) + 1e-5f);
            #pragma unroll
            for (int i = 0; i < 4; i++) {
                int c = i * 128 + lane * 4;
                float4 w4 = *(const float4*)&w[c];
                float4 b4 = *(const float4*)&bnb[c];
                float4 o4;
                o4.x = (v[i].x - mean) * inv * w4.x + b4.x;
                o4.y = (v[i].y - mean) * inv * w4.y + b4.y;
                o4.z = (v[i].z - mean) * inv * w4.z + b4.z;
                o4.w = (v[i].w - mean) * inv * w4.w + b4.w;
                *(float4*)&dst[(size_t)row * H + c] = o4;
            }
        }
    };

    // ---- Z0: zero scratch, broadcast queries, fold Wc/bc (warp-parallel) ----
    zero4(g_qkv[0], M * 3 * H);  zero4(g_qkv[1], M * 3 * H);
    zero4(g_qb[0],  M * H);      zero4(g_qb[1],  M * H);
    zero4(g_kv[0],  p.B * TCTX * 2 * H); zero4(g_kv[1], p.B * TCTX * 2 * H);
    zero4(g_so[0],  M * H);      zero4(g_so[1],  M * H);
    zero4(g_co[0],  M * H);      zero4(g_co[1],  M * H);
    zero4(g_hh[0],  M * FFD);    zero4(g_hh[1],  M * FFD);
    zero4(g_ff[0],  M * H);      zero4(g_ff[1],  M * H);
    zero4(g_Sa, p.B * p.Nobj * H); zero4(g_Sb, p.B * p.Nobj * H);
    zero4(g_Sc, M * H);
    for (int i = bid * NT + tid; i < M * H; i += GB * NT) {
        int row = i / H, c = i % H;
        g_x[i] = p.fq[(row % Fh) * H + c];
    }
    for (int u = gw; u < 27 * 16; u += GW) {
        int rr = u / 16, cgp = u % 16;
        const float* Pr = (rr < NPREDC) ? (p.pred_w + rr * H) : p.ex_w;
        int c = cgp * 32 + lane;
        float a0 = 0.f, a1 = 0.f, a2 = 0.f, a3 = 0.f;
        for (int n = 0; n < H; n += 4) {
            a0 += Pr[n]     * p.pe2_w[(size_t)n * H + c];
            a1 += Pr[n + 1] * p.pe2_w[(size_t)(n + 1) * H + c];
            a2 += Pr[n + 2] * p.pe2_w[(size_t)(n + 2) * H + c];
            a3 += Pr[n + 3] * p.pe2_w[(size_t)(n + 3) * H + c];
        }
        g_Wc[rr * H + c] = (a0 + a1) + (a2 + a3);
    }
    for (int u = gw; u < 27; u += GW) {
        const float* Pr = (u < NPREDC) ? (p.pred_w + u * H) : p.ex_w;
        float s = 0.f;
        for (int n = lane; n < H; n += 32) s += Pr[n] * p.pe2_b[n];
        #pragma unroll
        for (int o = 16; o; o >>= 1) s += __shfl_xor_sync(0xffffffffu, s, o);
        if (lane == 0) g_bc[u] = s + ((u < NPREDC) ? p.pred_b[u] : p.ex_b[0]);
    }
    gsync();

    // ---- S1: qkv0 + Sa + Sb + kv0 ----
    gemm_stage(g_x, H, nullptr, p.sa_in_w, H, g_qkv[0], 3 * H, M / 16, 3 * H / 128, 4);
    gemm_stage(p.objf, H, nullptr, p.pe1_w,     3 * H, g_Sa, H, (p.B * p.Nobj) / 16, 4, 4);
    gemm_stage(p.objf, H, nullptr, p.pe1_w + H, 3 * H, g_Sb, H, (p.B * p.Nobj) / 16, 4, 4);
    gemm_stage(p.tc, H, nullptr, p.ca_in_w + (size_t)H * H, H, g_kv[0], 2 * H, (p.B * TCTX) / 16, 2 * H / 128, 4);
    gsync();

    for (int l = 0; l < 2; l++) {
        const float* siw = p.sa_in_w  + (size_t)l * 3 * H * H;
        const float* sib = p.sa_in_b  + (size_t)l * 3 * H;
        const float* sow = p.sa_out_w + (size_t)l * H * H;
        const float* sob = p.sa_out_b + (size_t)l * H;
        const float* ciw = p.ca_in_w  + (size_t)l * 3 * H * H;
        const float* cib = p.ca_in_b  + (size_t)l * 3 * H;
        const float* cow = p.ca_out_w + (size_t)l * H * H;
        const float* cob = p.ca_out_b + (size_t)l * H;
        const float* f1w = p.ff1_w    + (size_t)l * FFD * H;
        const float* f1b = p.ff1_b    + (size_t)l * FFD;
        const float* f2w = p.ff2_w    + (size_t)l * H * FFD;
        const float* f2b = p.ff2_b    + (size_t)l * H;

        if (l == 1) {
            gemm_stage(g_x, H, nullptr, siw, H, g_qkv[1], 3 * H, M / 16, 3 * H / 128, 4);
            gemm_stage(p.tc, H, nullptr, ciw + (size_t)H * H, H, g_kv[1], 2 * H, (p.B * TCTX) / 16, 2 * H / 128, 4);
            gsync();
        }
        attn_stage(g_qkv[l], 3 * H, sib, g_qkv[l] + H, g_qkv[l] + 2 * H, 3 * H,
                   sib + H, sib + 2 * H, Fh, Fh);
        gsync();
        gemm_stage(g_ao, H, nullptr, sow, H, g_so[l], H, M / 16, 4, 4);
        gsync();
        ln_stage(g_so[l], g_x, sob, g_x, p.n1_w + l * H, p.n1_b + l * H);
        gsync();
        gemm_stage(g_x, H, nullptr, ciw, H, g_qb[l], H, M / 16, 4, 4);
        gsync();
        attn_stage(g_qb[l], H, cib, g_kv[l], g_kv[l] + H, 2 * H,
                   cib + H, cib + 2 * H, Fh, TCTX);
        gsync();
        gemm_stage(g_ao, H, nullptr, cow, H, g_co[l], H, M / 16, 4, 4);
        gsync();
        ln_stage(g_co[l], g_x, cob, g_x, p.n2_w + l * H, p.n2_b + l * H);
        gsync();
        gemm_stage(g_x, H, nullptr, f1w, H, g_hh[l], FFD, M / 16, FFD / 128, 4);
        gsync();
        gemm_stage(g_hh[l], FFD, f1b, f2w, FFD, g_ff[l], H, M / 16, 4, FFD / 128);
        gsync();
        ln_stage(g_ff[l], g_x, f2b, g_x, p.n3_w + l * H, p.n3_b + l * H);
        gsync();
    }

    ln_stage(g_x, nullptr, nullptr, g_ctx, p.norm_w, p.norm_b);
    gsync();
    gemm_stage(g_ctx, H, nullptr, p.pe1_w + 2 * H, 3 * H, g_Sc, H, M / 16, 4, 4);
}

// ------------------------- tiled final GEMM epilogue -------------------------
// block: 256 pairs x 32 r (27 real) for one bf; thread: 4 pairs x 8 r, k-packed fma2.
__global__ __launch_bounds__(256) void final_kernel(
    const float* __restrict__ pe1b,
    float* __restrict__ out_pred, float* __restrict__ out_ex,
    int Nobj, int P, int Fh)
{
    __shared__ float sG[32 * 260];     // [k in chunk][pair], pitch 260
    __shared__ float sWc[32 * 34];     // [r][k in chunk], pitch 34
    __shared__ float sSc[H];
    __shared__ int2  sIJ[256];
    int tid = threadIdx.x;
    int bf = blockIdx.y;
    int b = bf / Fh;
    int p0 = blockIdx.x * 256;

    for (int i = tid; i < H; i += 256) sSc[i] = g_Sc[(size_t)bf * H + i] + pe1b[i];
    {
        int nm1 = Nobj - 1;
        int pp = p0 + tid; if (pp >= P) pp = P - 1;
        int i = pp / nm1, r = pp % nm1; int j = (r < i) ? r : r + 1;
        sIJ[tid] = make_int2(i, j);
    }
    __syncthreads();

    const int pg = tid & 63;          // pairs 4pg..4pg+3
    const int rg = tid >> 6;          // r: 8rg..8rg+7
    float2 acc[4][8];
    #pragma unroll
    for (int q = 0; q < 4; q++)
        #pragma unroll
        for (int s = 0; s < 8; s++) acc[q][s] = make_float2(0.f, 0.f);

    const float* saRow = g_Sa + (size_t)(b * Nobj + sIJ[tid].x) * H;
    const float* sbRow = g_Sb + (size_t)(b * Nobj + sIJ[tid].y) * H;

    for (int kc = 0; kc < H; kc += 32) {
        #pragma unroll
        for (int j = 0; j < 4; j++) {
            int i = tid + j * 256;
            int r = i >> 5, k = i & 31;
            sWc[r * 34 + k] = (r < 27) ? g_Wc[r * H + kc + k] : 0.f;
        }
        #pragma unroll
        for (int j = 0; j < 8; j++) {
            int k = 4 * j;
            float4 a  = *(const float4*)(saRow + kc + k);
            float4 bv = *(const float4*)(sbRow + kc + k);
            float4 c4 = *(const float4*)(sSc + kc + k);
            sG[(k + 0) * 260 + tid] = gelu_f(a.x + bv.x + c4.x);
            sG[(k + 1) * 260 + tid] = gelu_f(a.y + bv.y + c4.y);
            sG[(k + 2) * 260 + tid] = gelu_f(a.z + bv.z + c4.z);
            sG[(k + 3) * 260 + tid] = gelu_f(a.w + bv.w + c4.w);
        }
        __syncthreads();
        #pragma unroll
        for (int kk = 0; kk < 16; kk++) {
            float4 gA = *(const float4*)&sG[(2 * kk)     * 260 + 4 * pg];
            float4 gB = *(const float4*)&sG[(2 * kk + 1) * 260 + 4 * pg];
            float2 gp[4] = { make_float2(gA.x, gB.x), make_float2(gA.y, gB.y),
                             make_float2(gA.z, gB.z), make_float2(gA.w, gB.w) };
            #pragma unroll
            for (int s = 0; s < 8; s++) {
                float2 w = *(const float2*)&sWc[(8 * rg + s) * 34 + 2 * kk];
                fma2(acc[0][s], gp[0], w);
                fma2(acc[1][s], gp[1], w);
                fma2(acc[2][s], gp[2], w);
                fma2(acc[3][s], gp[3], w);
            }
        }
        __syncthreads();
    }

    #pragma unroll
    for (int q = 0; q < 4; q++) {
        int pair = p0 + 4 * pg + q;
        if (pair >= P) continue;
        size_t base = (size_t)bf * P + pair;
        #pragma unroll
        for (int s = 0; s < 8; s++) {
            int r = 8 * rg + s;
            if (r >= 27) continue;
            float v = acc[q][s].x + acc[q][s].y + g_bc[r];
            if (r < NPREDC) out_pred[base * 26 + r] = v;
            else            out_ex[base] = v;
        }
    }
}

// ------------------------- host launcher -------------------------
extern "C" void kernel_launch(void* const* d_in, const int* in_sizes, int n_in,
                              void* d_out, int out_size)
{
    Params p;
    p.tc       = (const float*)d_in[0];
    p.objf     = (const float*)d_in[1];
    p.fq       = (const float*)d_in[2];
    p.sa_in_w  = (const float*)d_in[3];
    p.sa_in_b  = (const float*)d_in[4];
    p.sa_out_w = (const float*)d_in[5];
    p.sa_out_b = (const float*)d_in[6];
    p.ca_in_w  = (const float*)d_in[7];
    p.ca_in_b  = (const float*)d_in[8];
    p.ca_out_w = (const float*)d_in[9];
    p.ca_out_b = (const float*)d_in[10];
    p.ff1_w    = (const float*)d_in[11];
    p.ff1_b    = (const float*)d_in[12];
    p.ff2_w    = (const float*)d_in[13];
    p.ff2_b    = (const float*)d_in[14];
    p.n1_w     = (const float*)d_in[15];
    p.n1_b     = (const float*)d_in[16];
    p.n2_w     = (const float*)d_in[17];
    p.n2_b     = (const float*)d_in[18];
    p.n3_w     = (const float*)d_in[19];
    p.n3_b     = (const float*)d_in[20];
    p.norm_w   = (const float*)d_in[21];
    p.norm_b   = (const float*)d_in[22];
    p.pe1_w    = (const float*)d_in[23];
    p.pe1_b    = (const float*)d_in[24];
    p.pe2_w    = (const float*)d_in[25];
    p.pe2_b    = (const float*)d_in[26];
    p.pred_w   = (const float*)d_in[27];
    p.pred_b   = (const float*)d_in[28];
    p.ex_w     = (const float*)d_in[29];
    p.ex_b     = (const float*)d_in[30];

    p.B    = in_sizes[0] / (TCTX * H);
    p.Nobj = in_sizes[1] / (p.B * H);
    int P  = p.Nobj * (p.Nobj - 1);
    p.Fh   = out_size / (p.B * P * (NPREDC + 1));
    int M  = p.B * p.Fh;

    decoder_kernel<<<NB, NT>>>(p);

    float* out_pred = (float*)d_out;
    float* out_ex   = out_pred + (size_t)p.B * p.Fh * P * NPREDC;
    final_kernel<<<dim3((P + 255) / 256, M), 256>>>(p.pe1_b, out_pred, out_ex,
                                                    p.Nobj, P, p.Fh);
}

// round 8
// speedup vs baseline: 1.6180x; 1.1953x over previous
#include <cuda_runtime.h>
#include <math.h>

#define H    512
#define NH   8
#define DH   64
#define TCTX 10
#define FFD  2048
#define NPREDC 26
#define MAXB 16
#define MAXF 5
#define MAXN 20
#define NB   296
#define NT   256
#define PB   128   // pairs per final block
#define KZ   4     // final k-split

// ------------------------- device scratch -------------------------
__device__ float g_x  [MAXB * MAXF * H];
__device__ float g_ctx[MAXB * MAXF * H];
__device__ float g_qkv[2][MAXB * MAXF * 3 * H];
__device__ float g_qb [2][MAXB * MAXF * H];
__device__ float g_kv [2][MAXB * TCTX * 2 * H];
__device__ float g_ao [MAXB * MAXF * H];
__device__ float g_so [2][MAXB * MAXF * H];
__device__ float g_co [2][MAXB * MAXF * H];
__device__ float g_hh [2][MAXB * MAXF * FFD];
__device__ float g_ff [2][MAXB * MAXF * H];
__device__ float g_Sa [MAXB * MAXN * H];
__device__ float g_Sb [MAXB * MAXN * H];
__device__ float g_Sc [MAXB * MAXF * H];
__device__ float g_Wc [27 * H];
__device__ float g_bc [27];

__device__ unsigned g_count = 0;
__device__ unsigned g_gen   = 0;

struct Params {
    const float *tc, *objf, *fq;
    const float *sa_in_w, *sa_in_b, *sa_out_w, *sa_out_b;
    const float *ca_in_w, *ca_in_b, *ca_out_w, *ca_out_b;
    const float *ff1_w, *ff1_b, *ff2_w, *ff2_b;
    const float *n1_w, *n1_b, *n2_w, *n2_b, *n3_w, *n3_b, *norm_w, *norm_b;
    const float *pe1_w, *pe1_b, *pe2_w, *pe2_b, *pred_w, *pred_b, *ex_w, *ex_b;
    float *outp;     // d_out base (zeroed in Z0)
    int outn;        // out_size elements
    int B, Nobj, Fh;
};

__device__ __forceinline__ float gelu_f(float x) {
    return 0.5f * x * (1.0f + erff(x * 0.70710678118654752440f));
}

__device__ __forceinline__ void fma2(float2& d, float2 a, float2 b) {
    asm("fma.rn.f32x2 %0, %1, %2, %0;"
        : "+l"(reinterpret_cast<unsigned long long&>(d))
        : "l"(reinterpret_cast<unsigned long long&>(a)),
          "l"(reinterpret_cast<unsigned long long&>(b)));
}

__device__ __forceinline__ void gsync() {
    __syncthreads();
    if (threadIdx.x == 0) {
        __threadfence();
        unsigned gen = *((volatile unsigned*)&g_gen);
        if (atomicAdd(&g_count, 1) == gridDim.x - 1) {
            g_count = 0;
            __threadfence();
            atomicAdd(&g_gen, 1);
        } else {
            while (*((volatile unsigned*)&g_gen) == gen) { __nanosleep(32); }
            __threadfence();
        }
    }
    __syncthreads();
}

// ---- 16x128 GEMM tile over a 128-wide K slice, atomic out ----
__device__ void gemm_unit(const float* __restrict__ A, int lda, const float* __restrict__ ab,
                          const float* __restrict__ W, int ldw,
                          float* __restrict__ C, int ldc,
                          int row0, int n0, int kb,
                          float2* As2, float2* Ws2, int tid)
{
    const int rp = tid >> 5;
    const int cg = tid & 31;
    float2 acc[2][4];
    #pragma unroll
    for (int j = 0; j < 2; j++)
        #pragma unroll
        for (int q = 0; q < 4; q++) acc[j][q] = make_float2(0.f, 0.f);

    const int alr = tid >> 3, alk = tid & 7;
    const int wn  = tid >> 1, whf = tid & 1;
    float4 ar; float4 wr[4];

    auto loadRegs = [&](int k0) {
        if (tid < 128) {
            ar = *(const float4*)(A + (size_t)(row0 + alr) * lda + k0 + 4 * alk);
            if (ab) {
                const float* bb = ab + k0 + 4 * alk;
                ar.x = gelu_f(ar.x + bb[0]); ar.y = gelu_f(ar.y + bb[1]);
                ar.z = gelu_f(ar.z + bb[2]); ar.w = gelu_f(ar.w + bb[3]);
            }
        }
        const float* Wp = W + (size_t)(n0 + wn) * ldw + k0 + 16 * whf;
        #pragma unroll
        for (int i = 0; i < 4; i++) wr[i] = *(const float4*)(Wp + 4 * i);
    };
    auto storeRegs = [&]() {
        if (tid < 128) {
            As2[(2 * alk)     * 17 + alr] = make_float2(ar.x, ar.y);
            As2[(2 * alk + 1) * 17 + alr] = make_float2(ar.z, ar.w);
        }
        #pragma unroll
        for (int i = 0; i < 4; i++) {
            int kp = 8 * whf + 2 * i;
            Ws2[kp * 128 + wn]       = make_float2(wr[i].x, wr[i].y);
            Ws2[(kp + 1) * 128 + wn] = make_float2(wr[i].z, wr[i].w);
        }
    };

    loadRegs(kb);
    #pragma unroll
    for (int c = 0; c < 4; c++) {
        storeRegs();
        __syncthreads();
        if (c < 3) loadRegs(kb + 32 * (c + 1));
        #pragma unroll
        for (int kp = 0; kp < 16; kp++) {
            float2 a0 = As2[kp * 17 + 2 * rp];
            float2 a1 = As2[kp * 17 + 2 * rp + 1];
            const float4* wp4 = (const float4*)&Ws2[kp * 128 + 4 * cg];
            float4 w01 = wp4[0];
            float4 w23 = wp4[1];
            float2 wa = make_float2(w01.x, w01.y);
            float2 wb = make_float2(w01.z, w01.w);
            float2 wc = make_float2(w23.x, w23.y);
            float2 wd = make_float2(w23.z, w23.w);
            fma2(acc[0][0], a0, wa); fma2(acc[0][1], a0, wb);
            fma2(acc[0][2], a0, wc); fma2(acc[0][3], a0, wd);
            fma2(acc[1][0], a1, wa); fma2(acc[1][1], a1, wb);
            fma2(acc[1][2], a1, wc); fma2(acc[1][3], a1, wd);
        }
        __syncthreads();
    }

    int n = n0 + 4 * cg;
    #pragma unroll
    for (int j = 0; j < 2; j++) {
        float* Cp = C + (size_t)(row0 + 2 * rp + j) * ldc + n;
        atomicAdd(Cp + 0, acc[j][0].x + acc[j][0].y);
        atomicAdd(Cp + 1, acc[j][1].x + acc[j][1].y);
        atomicAdd(Cp + 2, acc[j][2].x + acc[j][2].y);
        atomicAdd(Cp + 3, acc[j][3].x + acc[j][3].y);
    }
}

// ------------------------- persistent decoder -------------------------
__global__ __launch_bounds__(NT, 2) void decoder_kernel(Params p)
{
    __shared__ float2 sA[16 * 17];
    __shared__ float2 sW[16 * 128];
    const int tid = threadIdx.x, bid = blockIdx.x;
    const int lane = tid & 31;
    const int gw = bid * (NT / 32) + (tid >> 5);
    const int GW = gridDim.x * (NT / 32);
    const int GB = gridDim.x;
    const int M = p.B * p.Fh;
    const int Fh = p.Fh;

    auto zero4 = [&](float* pz, int n) {
        float4* z = (float4*)pz;
        int t4 = n >> 2;
        for (int i = bid * NT + tid; i < t4; i += GB * NT)
            z[i] = make_float4(0.f, 0.f, 0.f, 0.f);
    };
    auto gemm_stage = [&](const float* A, int lda, const float* ab,
                          const float* W, int ldw, float* C, int ldc,
                          int mt, int nt, int kz) {
        int total = mt * nt * kz;
        for (int u = bid; u < total; u += GB) {
            int m = u % mt; int n = (u / mt) % nt; int z = u / (mt * nt);
            gemm_unit(A, lda, ab, W, ldw, C, ldc, m * 16, n * 128, z * 128, sA, sW, tid);
        }
    };
    auto attn_stage = [&](const float* Q, int ldq, const float* qb,
                          const float* K, const float* V, int ldkv,
                          const float* kb, const float* vb, int Tq, int Tk) {
        for (int u = gw; u < p.B * NH * Tq; u += GW) {
            int qi = u % Tq; int h = (u / Tq) % NH; int b = u / (Tq * NH);
            const float* qrow = Q + (size_t)(b * Tq + qi) * ldq + h * DH;
            float q0 = qrow[lane]      + qb[h * DH + lane];
            float q1 = qrow[lane + 32] + qb[h * DH + lane + 32];
            float kb0 = kb[h * DH + lane], kb1 = kb[h * DH + lane + 32];
            float vb0 = vb[h * DH + lane], vb1 = vb[h * DH + lane + 32];
            float s[TCTX];
            #pragma unroll
            for (int k = 0; k < TCTX; k++) {
                if (k < Tk) {
                    const float* krow = K + (size_t)(b * Tk + k) * ldkv + h * DH;
                    float pr = q0 * (krow[lane] + kb0) + q1 * (krow[lane + 32] + kb1);
                    #pragma unroll
                    for (int o = 16; o; o >>= 1) pr += __shfl_xor_sync(0xffffffffu, pr, o);
                    s[k] = pr * 0.125f;
                }
            }
            float mx = -1e30f;
            #pragma unroll
            for (int k = 0; k < TCTX; k++) if (k < Tk) mx = fmaxf(mx, s[k]);
            float sum = 0.f;
            #pragma unroll
            for (int k = 0; k < TCTX; k++) if (k < Tk) { s[k] = expf(s[k] - mx); sum += s[k]; }
            float inv = 1.f / sum;
            float o0 = 0.f, o1 = 0.f;
            #pragma unroll
            for (int k = 0; k < TCTX; k++) {
                if (k < Tk) {
                    const float* vrow = V + (size_t)(b * Tk + k) * ldkv + h * DH;
                    float a = s[k] * inv;
                    o0 += a * (vrow[lane] + vb0);
                    o1 += a * (vrow[lane + 32] + vb1);
                }
            }
            float* orow = g_ao + (size_t)(b * Tq + qi) * H + h * DH;
            orow[lane]      = o0;
            orow[lane + 32] = o1;
        }
    };
    auto ln_stage = [&](const float* src, const float* res, const float* cb,
                        float* dst, const float* w, const float* bnb) {
        for (int row = gw; row < M; row += GW) {
            const float* xr = src + (size_t)row * H;
            float4 v[4];
            float s = 0.f;
            #pragma unroll
            for (int i = 0; i < 4; i++) {
                int c = i * 128 + lane * 4;
                float4 t = *(const float4*)&xr[c];
                if (res) { float4 r = *(const float4*)&res[(size_t)row * H + c];
                           t.x += r.x; t.y += r.y; t.z += r.z; t.w += r.w; }
                if (cb)  { float4 b4 = *(const float4*)&cb[c];
                           t.x += b4.x; t.y += b4.y; t.z += b4.z; t.w += b4.w; }
                v[i] = t; s += t.x + t.y + t.z + t.w;
            }
            #pragma unroll
            for (int o = 16; o; o >>= 1) s += __shfl_xor_sync(0xffffffffu, s, o);
            float mean = s * (1.0f / H);
            float q = 0.f;
            #pragma unroll
            for (int i = 0; i < 4; i++) {
                float dx = v[i].x - mean, dy = v[i].y - mean, dz = v[i].z - mean, dw = v[i].w - mean;
                q += dx * dx + dy * dy + dz * dz + dw * dw;
            }
            #pragma unroll
            for (int o = 16; o; o >>= 1) q += __shfl_xor_sync(0xffffffffu, q, o);
            float inv = 1.0f / sqrtf(q * (1.0f / H) + 1e-5f);
            #pragma unroll
            for (int i = 0; i < 4; i++) {
                int c = i * 128 + lane * 4;
                float4 w4 = *(const float4*)&w[c];
                float4 b4 = *(const float4*)&bnb[c];
                float4 o4;
                o4.x = (v[i].x - mean) * inv * w4.x + b4.x;
                o4.y = (v[i].y - mean) * inv * w4.y + b4.y;
                o4.z = (v[i].z - mean) * inv * w4.z + b4.z;
                o4.w = (v[i].w - mean) * inv * w4.w + b4.w;
                *(float4*)&dst[(size_t)row * H + c] = o4;
            }
        }
    };

    // ---- Z0: zero scratch + d_out, broadcast queries, fold Wc/bc ----
    zero4(g_qkv[0], M * 3 * H);  zero4(g_qkv[1], M * 3 * H);
    zero4(g_qb[0],  M * H);      zero4(g_qb[1],  M * H);
    zero4(g_kv[0],  p.B * TCTX * 2 * H); zero4(g_kv[1], p.B * TCTX * 2 * H);
    zero4(g_so[0],  M * H);      zero4(g_so[1],  M * H);
    zero4(g_co[0],  M * H);      zero4(g_co[1],  M * H);
    zero4(g_hh[0],  M * FFD);    zero4(g_hh[1],  M * FFD);
    zero4(g_ff[0],  M * H);      zero4(g_ff[1],  M * H);
    zero4(g_Sa, p.B * p.Nobj * H); zero4(g_Sb, p.B * p.Nobj * H);
    zero4(g_Sc, M * H);
    zero4(p.outp, p.outn);
    for (int i = bid * NT + tid; i < M * H; i += GB * NT) {
        int row = i / H, c = i % H;
        g_x[i] = p.fq[(row % Fh) * H + c];
    }
    for (int u = gw; u < 27 * 16; u += GW) {
        int rr = u / 16, cgp = u % 16;
        const float* Pr = (rr < NPREDC) ? (p.pred_w + rr * H) : p.ex_w;
        int c = cgp * 32 + lane;
        float a0 = 0.f, a1 = 0.f, a2 = 0.f, a3 = 0.f;
        for (int n = 0; n < H; n += 4) {
            a0 += Pr[n]     * p.pe2_w[(size_t)n * H + c];
            a1 += Pr[n + 1] * p.pe2_w[(size_t)(n + 1) * H + c];
            a2 += Pr[n + 2] * p.pe2_w[(size_t)(n + 2) * H + c];
            a3 += Pr[n + 3] * p.pe2_w[(size_t)(n + 3) * H + c];
        }
        g_Wc[rr * H + c] = (a0 + a1) + (a2 + a3);
    }
    for (int u = gw; u < 27; u += GW) {
        const float* Pr = (u < NPREDC) ? (p.pred_w + u * H) : p.ex_w;
        float s = 0.f;
        for (int n = lane; n < H; n += 32) s += Pr[n] * p.pe2_b[n];
        #pragma unroll
        for (int o = 16; o; o >>= 1) s += __shfl_xor_sync(0xffffffffu, s, o);
        if (lane == 0) g_bc[u] = s + ((u < NPREDC) ? p.pred_b[u] : p.ex_b[0]);
    }
    gsync();

    // ---- S1: qkv0 + Sa + Sb + kv0 ----
    gemm_stage(g_x, H, nullptr, p.sa_in_w, H, g_qkv[0], 3 * H, M / 16, 3 * H / 128, 4);
    gemm_stage(p.objf, H, nullptr, p.pe1_w,     3 * H, g_Sa, H, (p.B * p.Nobj) / 16, 4, 4);
    gemm_stage(p.objf, H, nullptr, p.pe1_w + H, 3 * H, g_Sb, H, (p.B * p.Nobj) / 16, 4, 4);
    gemm_stage(p.tc, H, nullptr, p.ca_in_w + (size_t)H * H, H, g_kv[0], 2 * H, (p.B * TCTX) / 16, 2 * H / 128, 4);
    gsync();

    for (int l = 0; l < 2; l++) {
        const float* siw = p.sa_in_w  + (size_t)l * 3 * H * H;
        const float* sib = p.sa_in_b  + (size_t)l * 3 * H;
        const float* sow = p.sa_out_w + (size_t)l * H * H;
        const float* sob = p.sa_out_b + (size_t)l * H;
        const float* ciw = p.ca_in_w  + (size_t)l * 3 * H * H;
        const float* cib = p.ca_in_b  + (size_t)l * 3 * H;
        const float* cow = p.ca_out_w + (size_t)l * H * H;
        const float* cob = p.ca_out_b + (size_t)l * H;
        const float* f1w = p.ff1_w    + (size_t)l * FFD * H;
        const float* f1b = p.ff1_b    + (size_t)l * FFD;
        const float* f2w = p.ff2_w    + (size_t)l * H * FFD;
        const float* f2b = p.ff2_b    + (size_t)l * H;

        if (l == 1) {
            gemm_stage(g_x, H, nullptr, siw, H, g_qkv[1], 3 * H, M / 16, 3 * H / 128, 4);
            gemm_stage(p.tc, H, nullptr, ciw + (size_t)H * H, H, g_kv[1], 2 * H, (p.B * TCTX) / 16, 2 * H / 128, 4);
            gsync();
        }
        attn_stage(g_qkv[l], 3 * H, sib, g_qkv[l] + H, g_qkv[l] + 2 * H, 3 * H,
                   sib + H, sib + 2 * H, Fh, Fh);
        gsync();
        gemm_stage(g_ao, H, nullptr, sow, H, g_so[l], H, M / 16, 4, 4);
        gsync();
        ln_stage(g_so[l], g_x, sob, g_x, p.n1_w + l * H, p.n1_b + l * H);
        gsync();
        gemm_stage(g_x, H, nullptr, ciw, H, g_qb[l], H, M / 16, 4, 4);
        gsync();
        attn_stage(g_qb[l], H, cib, g_kv[l], g_kv[l] + H, 2 * H,
                   cib + H, cib + 2 * H, Fh, TCTX);
        gsync();
        gemm_stage(g_ao, H, nullptr, cow, H, g_co[l], H, M / 16, 4, 4);
        gsync();
        ln_stage(g_co[l], g_x, cob, g_x, p.n2_w + l * H, p.n2_b + l * H);
        gsync();
        gemm_stage(g_x, H, nullptr, f1w, H, g_hh[l], FFD, M / 16, FFD / 128, 4);
        gsync();
        gemm_stage(g_hh[l], FFD, f1b, f2w, FFD, g_ff[l], H, M / 16, 4, FFD / 128);
        gsync();
        ln_stage(g_ff[l], g_x, f2b, g_x, p.n3_w + l * H, p.n3_b + l * H);
        gsync();
    }

    ln_stage(g_x, nullptr, nullptr, g_ctx, p.norm_w, p.norm_b);
    gsync();
    gemm_stage(g_ctx, H, nullptr, p.pe1_w + 2 * H, 3 * H, g_Sc, H, M / 16, 4, 4);
}

// ------------------------- final epilogue: split-K pair GEMM -------------------------
// grid (ceil(P/PB), M, KZ); block 256. Each block: PB pairs x 27 r over 128 k.
// Thread tile 4 pairs x 4 r; atomicAdd into pre-zeroed d_out; z==0 adds bias.
__global__ __launch_bounds__(256) void final_kernel(
    const float* __restrict__ pe1b,
    float* __restrict__ out_pred, float* __restrict__ out_ex,
    int Nobj, int P, int Fh)
{
    __shared__ float sG[32 * (PB + 4)];   // [k][pair], pitch PB+4
    __shared__ float sWc[32 * 34];        // [r][k], pitch 34
    __shared__ float sSc[128];
    __shared__ int2  sIJ[PB];
    const int tid = threadIdx.x;
    const int bf = blockIdx.y;
    const int b = bf / Fh;
    const int p0 = blockIdx.x * PB;
    const int kz0 = blockIdx.z * (H / KZ);     // 128-wide k range

    for (int i = tid; i < 128; i += 256) sSc[i] = g_Sc[(size_t)bf * H + kz0 + i] + pe1b[kz0 + i];
    if (tid < PB) {
        int nm1 = Nobj - 1;
        int pp = p0 + tid; if (pp >= P) pp = P - 1;
        int i = pp / nm1, r = pp % nm1; int j = (r < i) ? r : r + 1;
        sIJ[tid] = make_int2(i, j);
    }
    __syncthreads();

    const int spair = tid >> 1;              // staging: pair 0..127
    const int skh   = tid & 1;               // staging: k half (16 k each)
    const float* saRow = g_Sa + (size_t)(b * Nobj + sIJ[spair].x) * H + kz0;
    const float* sbRow = g_Sb + (size_t)(b * Nobj + sIJ[spair].y) * H + kz0;

    const int pg = tid & 31;                 // pairs 4pg..4pg+3
    const int rg = tid >> 5;                 // r: 4rg..4rg+3
    float2 acc[4][4];
    #pragma unroll
    for (int q = 0; q < 4; q++)
        #pragma unroll
        for (int s = 0; s < 4; s++) acc[q][s] = make_float2(0.f, 0.f);

    for (int kc = 0; kc < 128; kc += 32) {
        // stage Wc chunk (27 rows padded to 32)
        #pragma unroll
        for (int j = 0; j < 4; j++) {
            int i = tid + j * 256;
            int r = i >> 5, k = i & 31;
            sWc[r * 34 + k] = (r < 27) ? g_Wc[r * H + kz0 + kc + k] : 0.f;
        }
        // stage gelu(Sa+Sb+Sc): each thread 16 k for its pair
        #pragma unroll
        for (int j = 0; j < 4; j++) {
            int k = skh * 16 + j * 4;
            float4 a  = *(const float4*)(saRow + kc + k);
            float4 bv = *(const float4*)(sbRow + kc + k);
            float4 c4 = *(const float4*)(sSc + kc + k);
            sG[(k + 0) * (PB + 4) + spair] = gelu_f(a.x + bv.x + c4.x);
            sG[(k + 1) * (PB + 4) + spair] = gelu_f(a.y + bv.y + c4.y);
            sG[(k + 2) * (PB + 4) + spair] = gelu_f(a.z + bv.z + c4.z);
            sG[(k + 3) * (PB + 4) + spair] = gelu_f(a.w + bv.w + c4.w);
        }
        __syncthreads();
        #pragma unroll
        for (int kk = 0; kk < 16; kk++) {
            float4 gA = *(const float4*)&sG[(2 * kk)     * (PB + 4) + 4 * pg];
            float4 gB = *(const float4*)&sG[(2 * kk + 1) * (PB + 4) + 4 * pg];
            float2 gp[4] = { make_float2(gA.x, gB.x), make_float2(gA.y, gB.y),
                             make_float2(gA.z, gB.z), make_float2(gA.w, gB.w) };
            #pragma unroll
            for (int s = 0; s < 4; s++) {
                float2 w = *(const float2*)&sWc[(4 * rg + s) * 34 + 2 * kk];
                fma2(acc[0][s], gp[0], w);
                fma2(acc[1][s], gp[1], w);
                fma2(acc[2][s], gp[2], w);
                fma2(acc[3][s], gp[3], w);
            }
        }
        __syncthreads();
    }

    const float biasOn = (blockIdx.z == 0) ? 1.f : 0.f;
    #pragma unroll
    for (int q = 0; q < 4; q++) {
        int pair = p0 + 4 * pg + q;
        if (pair >= P) continue;
        size_t base = (size_t)bf * P + pair;
        #pragma unroll
        for (int s = 0; s < 4; s++) {
            int r = 4 * rg + s;
            if (r >= 27) continue;
            float v = acc[q][s].x + acc[q][s].y + biasOn * g_bc[r];
            if (r < NPREDC) atomicAdd(&out_pred[base * 26 + r], v);
            else            atomicAdd(&out_ex[base], v);
        }
    }
}

// ------------------------- host launcher -------------------------
extern "C" void kernel_launch(void* const* d_in, const int* in_sizes, int n_in,
                              void* d_out, int out_size)
{
    Params p;
    p.tc       = (const float*)d_in[0];
    p.objf     = (const float*)d_in[1];
    p.fq       = (const float*)d_in[2];
    p.sa_in_w  = (const float*)d_in[3];
    p.sa_in_b  = (const float*)d_in[4];
    p.sa_out_w = (const float*)d_in[5];
    p.sa_out_b = (const float*)d_in[6];
    p.ca_in_w  = (const float*)d_in[7];
    p.ca_in_b  = (const float*)d_in[8];
    p.ca_out_w = (const float*)d_in[9];
    p.ca_out_b = (const float*)d_in[10];
    p.ff1_w    = (const float*)d_in[11];
    p.ff1_b    = (const float*)d_in[12];
    p.ff2_w    = (const float*)d_in[13];
    p.ff2_b    = (const float*)d_in[14];
    p.n1_w     = (const float*)d_in[15];
    p.n1_b     = (const float*)d_in[16];
    p.n2_w     = (const float*)d_in[17];
    p.n2_b     = (const float*)d_in[18];
    p.n3_w     = (const float*)d_in[19];
    p.n3_b     = (const float*)d_in[20];
    p.norm_w   = (const float*)d_in[21];
    p.norm_b   = (const float*)d_in[22];
    p.pe1_w    = (const float*)d_in[23];
    p.pe1_b    = (const float*)d_in[24];
    p.pe2_w    = (const float*)d_in[25];
    p.pe2_b    = (const float*)d_in[26];
    p.pred_w   = (const float*)d_in[27];
    p.pred_b   = (const float*)d_in[28];
    p.ex_w     = (const float*)d_in[29];
    p.ex_b     = (const float*)d_in[30];

    p.B    = in_sizes[0] / (TCTX * H);
    p.Nobj = in_sizes[1] / (p.B * H);
    int P  = p.Nobj * (p.Nobj - 1);
    p.Fh   = out_size / (p.B * P * (NPREDC + 1));
    int M  = p.B * p.Fh;
    p.outp = (float*)d_out;
    p.outn = out_size;

    decoder_kernel<<<NB, NT>>>(p);

    float* out_pred = (float*)d_out;
    float* out_ex   = out_pred + (size_t)p.B * p.Fh * P * NPREDC;
    final_kernel<<<dim3((P + PB - 1) / PB, M, KZ), 256>>>(p.pe1_b, out_pred, out_ex,
                                                          p.Nobj, P, p.Fh);
}